// round 3
// baseline (speedup 1.0000x reference)
#include <cuda_runtime.h>
#include <math.h>

#define BS    512
#define LNUM  68
#define IMG   224
#define RS    7
#define R2    49
#define LL    (LNUM * LNUM)     // 4624
#define NTHR  544               // 17 warps, 4 landmarks per warp
#define FULLM 0xFFFFFFFFu
#define MB    0x1FFFFu          // lanes 0..16 hold slots 32..48

__device__ double   g_sumL = 0.0;
__device__ double   g_sumM = 0.0;
__device__ unsigned g_done = 0u;

// Sample one region slot s (0..48); exact replica of the reference's
// grid_sample-nearest arithmetic (rintf == jnp.round, half-even).
__device__ __forceinline__ float region_val(const float* __restrict__ dimg,
                                            float fx, float fy, int s)
{
    int p = s / RS, q = s - p * RS;
    float xp = (p == RS - 1) ? 3.5f : (-3.5f + (float)p * (7.0f / 6.0f));
    float xq = (q == RS - 1) ? 3.5f : (-3.5f + (float)q * (7.0f / 6.0f));
    xp = xp / 224.0f * 2.0f;
    xq = xq / 224.0f * 2.0f;
    float gy = fy + xp;                       // offsets[p][q] = (x[q], x[p])
    float gx = fx + xq;
    float iy = ((gy + 1.0f) * 224.0f - 1.0f) * 0.5f;
    float ix = ((gx + 1.0f) * 224.0f - 1.0f) * 0.5f;
    int yi = (int)rintf(iy);
    int xi = (int)rintf(ix);
    bool v = (yi >= 0) & (yi < IMG) & (xi >= 0) & (xi < IMG);
    int yc = min(max(yi, 0), IMG - 1);
    int xc = min(max(xi, 0), IMG - 1);
    float val = __ldg(dimg + yc * IMG + xc);
    return v ? val : 0.0f;
}

__global__ __launch_bounds__(NTHR) void fused_kernel(
    const float* __restrict__ rel,
    const float* __restrict__ depth,
    const float* __restrict__ lm,
    const float* __restrict__ sf,
    const float* __restrict__ bbox,
    float* __restrict__ out)
{
    __shared__ float  smed[LNUM];
    __shared__ float  smask[LNUM];
    __shared__ float  s_mom;
    __shared__ double redL[17], redM[17];
    __shared__ bool   s_last;

    int b    = blockIdx.x;
    int tid  = threadIdx.x;
    int wid  = tid >> 5;
    int lane = tid & 31;

    float sf0 = sf[b * 2 + 0], sf1 = sf[b * 2 + 1];
    float bx  = bbox[b * 4 + 0], by = bbox[b * 4 + 1];
    const float* dimg = depth + (size_t)b * IMG * IMG;
    const float  INF  = __int_as_float(0x7f800000);

    // ---- phase 1: gather 49 region values per landmark (4 landmarks/warp) ----
    float v0[4], v1[4];
#pragma unroll
    for (int li = 0; li < 4; li++) {
        int l = wid * 4 + li;
        float lmx = lm[((size_t)b * LNUM + l) * 2 + 0];
        float lmy = lm[((size_t)b * LNUM + l) * 2 + 1];
        float fx = (lmx - bx) * sf0 / 224.0f * 2.0f - 1.0f;
        float fy = (lmy - by) * sf1 / 224.0f * 2.0f - 1.0f;
        v0[li] = region_val(dimg, fx, fy, lane);
        v1[li] = (lane < 17) ? region_val(dimg, fx, fy, lane + 32) : INF;
    }

    // ---- 4-way interleaved warp quickselect (rank mi per landmark) ----
    // mi = (clamp(count(v<=THR),1,48)+48)/2 — the reference's sorted-region
    // median with the transition-index rule. All state is warp-uniform.
    unsigned a0[4], a1[4];
    int      mi[4];
    float    res[4];
#pragma unroll
    for (int li = 0; li < 4; li++) {
        unsigned le0 = __ballot_sync(FULLM, v0[li] <= 1e-4f);
        unsigned le1 = __ballot_sync(FULLM, v1[li] <= 1e-4f) & MB;
        int k  = __popc(le0) + __popc(le1);
        int st = min(max(k, 1), R2 - 1);
        mi[li] = (st + R2 - 1) >> 1;
        a0[li] = FULLM;
        a1[li] = MB;
    }
    unsigned act = 0xFu;
    while (act) {
#pragma unroll
        for (int li = 0; li < 4; li++) {
            if (act & (1u << li)) {
                bool  use0 = (a0[li] != 0u);
                int   pl   = use0 ? (__ffs(a0[li]) - 1) : (__ffs(a1[li]) - 1);
                float pa   = __shfl_sync(FULLM, v0[li], pl);
                float pb   = __shfl_sync(FULLM, v1[li], pl);
                float piv  = use0 ? pa : pb;
                unsigned l0  = __ballot_sync(FULLM, v0[li] <  piv);
                unsigned l1  = __ballot_sync(FULLM, v1[li] <  piv) & MB;
                unsigned le0 = __ballot_sync(FULLM, v0[li] <= piv);
                unsigned le1 = __ballot_sync(FULLM, v1[li] <= piv) & MB;
                int cl = __popc(l0)  + __popc(l1);
                int ce = __popc(le0) + __popc(le1);
                if (mi[li] >= cl && mi[li] < ce) {
                    res[li] = piv;
                    act &= ~(1u << li);
                } else if (mi[li] < cl) {
                    a0[li] &= l0;    a1[li] &= l1;
                } else {
                    a0[li] &= ~le0;  a1[li] &= ~le1;
                }
            }
        }
    }
    if (lane == 0) {
#pragma unroll
        for (int li = 0; li < 4; li++) smed[wid * 4 + li] = res[li];
    }
    __syncthreads();

    // ---- phase 2: lower median-of-medians (rank 33) + mask, in-block ----
    float vraw = 0.0f;
    if (tid < LNUM) {
        vraw = smed[tid];
        int r = 0;
#pragma unroll 4
        for (int j = 0; j < LNUM; j++) {
            float w = smed[j];
            r += (w < vraw || (w == vraw && j < tid)) ? 1 : 0;  // stable rank
        }
        if (r == (LNUM - 1) / 2) s_mom = vraw;
    }
    __syncthreads();
    if (tid < LNUM) {
        smask[tid] = (fabsf(vraw - s_mom) < (90.0f / 500.0f)) ? 1.0f : 0.0f;
        smed[tid]  = vraw * 500.0f;
    }
    __syncthreads();

    // ---- phase 3: pairwise diff / mask / smooth-L1, vectorized stores ----
    // Output layout: out[0]=loss, outd=out+1, outm=out+1+BS*LL.
    // Global float index of outd[base+e] is 1+base+e; base%4==0, so e≡3 (mod 4)
    // gives 16B-aligned float4 stores. Per batch: 3 scalar head, 1155 vec4
    // groups (e=3..4622), 1 scalar tail (e=4623).
    float* outd = out + 1;
    float* outm = out + 1 + (size_t)BS * LL;
    const size_t base = (size_t)b * LL;
    const float* relb = rel + base;
    float accL = 0.0f, accM = 0.0f;

    if (tid < 4) {                      // head e=0,1,2 and tail e=4623
        int e = (tid < 3) ? tid : (LL - 1);
        int i = e / LNUM;
        int j = e - i * LNUM;
        float diff = smed[i] - smed[j];
        float mk   = smask[i] * smask[j];
        float d    = relb[e] - diff;
        float ad   = fabsf(d);
        float c    = fminf(ad, 1.0f);
        float le   = c * (ad - 0.5f * c);
        outd[base + e] = diff;
        outm[base + e] = mk;
        accL += le * mk;
        accM += mk;
    }

    const int NGRP = (LL - 4) / 4;      // 1155
    for (int g = tid; g < NGRP; g += NTHR) {
        int e0 = 3 + (g << 2);
        int i0 = e0 / LNUM;
        int j0 = e0 - i0 * LNUM;
        float4 dv, mv;
        float dvv[4], mvv[4];
#pragma unroll
        for (int n = 0; n < 4; n++) {
            int jn = j0 + n;
            int wrap = (jn >= LNUM) ? 1 : 0;
            int in = i0 + wrap;
            jn -= LNUM * wrap;
            float diff = smed[in] - smed[jn];
            float mk   = smask[in] * smask[jn];
            float d    = relb[e0 + n] - diff;
            float ad   = fabsf(d);
            float c    = fminf(ad, 1.0f);
            float le   = c * (ad - 0.5f * c);
            dvv[n] = diff;
            mvv[n] = mk;
            accL += le * mk;
            accM += mk;
        }
        dv = make_float4(dvv[0], dvv[1], dvv[2], dvv[3]);
        mv = make_float4(mvv[0], mvv[1], mvv[2], mvv[3]);
        *reinterpret_cast<float4*>(outd + base + e0) = dv;
        *reinterpret_cast<float4*>(outm + base + e0) = mv;
    }

    // ---- block reduce (double) + global atomics ----
    double dL = (double)accL, dM = (double)accM;
#pragma unroll
    for (int o = 16; o > 0; o >>= 1) {
        dL += __shfl_down_sync(FULLM, dL, o);
        dM += __shfl_down_sync(FULLM, dM, o);
    }
    if (lane == 0) { redL[wid] = dL; redM[wid] = dM; }
    __syncthreads();
    if (tid == 0) {
        double tL = 0.0, tM = 0.0;
#pragma unroll
        for (int w = 0; w < 17; w++) { tL += redL[w]; tM += redM[w]; }
        atomicAdd(&g_sumL, tL);
        atomicAdd(&g_sumM, tM);
        __threadfence();
        unsigned n = atomicAdd(&g_done, 1u);
        s_last = (n == BS - 1);
    }
    __syncthreads();

    // ---- last block finalizes scalar loss and resets state for next replay ----
    if (s_last && tid == 0) {
        __threadfence();
        double L = g_sumL, M = g_sumM;
        out[0] = (float)(L / (M + 1e-4));
        g_sumL = 0.0; g_sumM = 0.0; g_done = 0u;
    }
}

extern "C" void kernel_launch(void* const* d_in, const int* in_sizes, int n_in,
                              void* d_out, int out_size)
{
    const float* rel   = (const float*)d_in[0];   // [BS, L, L]
    const float* depth = (const float*)d_in[1];   // [BS, 1, IMG, IMG]
    const float* lm    = (const float*)d_in[2];   // [BS, L, 2]
    const float* sf    = (const float*)d_in[3];   // [BS, 2]
    const float* bbox  = (const float*)d_in[4];   // [BS, 4]
    float* out = (float*)d_out;                   // [loss | diff | mask]

    fused_kernel<<<BS, NTHR>>>(rel, depth, lm, sf, bbox, out);
}